// round 2
// baseline (speedup 1.0000x reference)
#include <cuda_runtime.h>
#include <math.h>

#define B_  2
#define L_  768
#define E_  768
#define H_  12
#define DH_ 64
#define D_  8
#define DS_ 8
#define INV_SQRT_DS 0.35355339059327373f
#define ALPHA_ 2.5f

// ---------------- scratch (static device globals; no allocation) -------------
__device__ float  g_Q[B_*H_*L_*DH_];
__device__ float  g_K[B_*H_*L_*DH_];
__device__ float  g_V[B_*H_*L_*DH_];
__device__ float  g_mS[B_*H_*D_*L_*2];   // per (b,h,d,q): rowmax m, denom S
__device__ double g_acc[B_*D_*4];        // sums over (h,q): var, max, hhi, ent
__device__ float  g_w[B_*D_];            // depth gate weights

// ============================================================================
// K1: fused Q/K/V projections.  X[1536,768] @ W[768,768] + b, written as
// [b][h][l][dh].  128x64 output tiles, BK=8, 256 threads, 8x4 per thread.
// blockIdx.z selects which of {Q,K,V}.
// ============================================================================
#define PBM 128
#define PBN 64
#define PBK 8

__global__ __launch_bounds__(256) void proj_kernel(
    const float* __restrict__ X,
    const float* __restrict__ Wq, const float* __restrict__ bq,
    const float* __restrict__ Wk, const float* __restrict__ bk,
    const float* __restrict__ Wv, const float* __restrict__ bv)
{
    __shared__ float As[PBK][PBM];
    __shared__ float Bs[PBK][PBN];
    const int t = threadIdx.x;

    if (blockIdx.x == 0 && blockIdx.y == 0 && blockIdx.z == 0 && t < B_*D_*4)
        g_acc[t] = 0.0;

    const float* W; const float* bias; float* out;
    if (blockIdx.z == 0)      { W = Wq; bias = bq; out = g_Q; }
    else if (blockIdx.z == 1) { W = Wk; bias = bk; out = g_K; }
    else                      { W = Wv; bias = bv; out = g_V; }

    const int row0 = blockIdx.y * PBM;
    const int col0 = blockIdx.x * PBN;
    const int ty = t >> 4, tx = t & 15;

    float acc[8][4];
    #pragma unroll
    for (int i = 0; i < 8; i++)
        #pragma unroll
        for (int j = 0; j < 4; j++) acc[i][j] = 0.f;

    const int am = t >> 1, akq = (t & 1) * 4;

    for (int kk = 0; kk < E_; kk += PBK) {
        float4 av = *reinterpret_cast<const float4*>(&X[(size_t)(row0 + am) * E_ + kk + akq]);
        As[akq + 0][am] = av.x; As[akq + 1][am] = av.y;
        As[akq + 2][am] = av.z; As[akq + 3][am] = av.w;
        if (t < 128) {
            int bkk = t >> 4, bn4 = (t & 15) * 4;
            *reinterpret_cast<float4*>(&Bs[bkk][bn4]) =
                *reinterpret_cast<const float4*>(&W[(size_t)(kk + bkk) * E_ + col0 + bn4]);
        }
        __syncthreads();
        #pragma unroll
        for (int k = 0; k < PBK; k++) {
            float a[8], b4[4];
            #pragma unroll
            for (int i = 0; i < 8; i++) a[i] = As[k][ty * 8 + i];
            #pragma unroll
            for (int j = 0; j < 4; j++) b4[j] = Bs[k][tx * 4 + j];
            #pragma unroll
            for (int i = 0; i < 8; i++)
                #pragma unroll
                for (int j = 0; j < 4; j++)
                    acc[i][j] = fmaf(a[i], b4[j], acc[i][j]);
        }
        __syncthreads();
    }

    const int h = col0 / DH_;          // PBN == DH_ so a block is one head
    #pragma unroll
    for (int i = 0; i < 8; i++) {
        int row = row0 + ty * 8 + i;
        int b = row / L_, l = row % L_;
        float4 o;
        o.x = acc[i][0] + bias[col0 + tx * 4 + 0];
        o.y = acc[i][1] + bias[col0 + tx * 4 + 1];
        o.z = acc[i][2] + bias[col0 + tx * 4 + 2];
        o.w = acc[i][3] + bias[col0 + tx * 4 + 3];
        *reinterpret_cast<float4*>(&out[(size_t)((b * H_ + h) * L_ + l) * DH_ + tx * 4]) = o;
    }
}

// ============================================================================
// K2: per-row online softmax statistics for one (b,h,d).
// grid.x = B*H*D (192), grid.y = L/32 (24).  8 warps x 4 rows = 32 q rows.
// Each lane walks k = lane, lane+32, ... with running (m, S, E1, E2);
// butterfly merge; analytic stats; double atomics into g_acc.
//   maxp = 1/S, hhi = E2/S^2, var = (hhi - 1/L)/(L-1),
//   ent  = log S - E1/S   with E1 = sum e_i (s_i - m)
// ============================================================================
__global__ __launch_bounds__(256) void stats_kernel(const float* __restrict__ mask)
{
    __shared__ float sk[L_ * 12];     // K slice [768][8] padded to 12
    __shared__ float sq[32 * 8];
    __shared__ float smask[L_];
    __shared__ float sred[8][4];

    const int t = threadIdx.x;
    const int bhd = blockIdx.x;
    const int d = bhd & 7;
    const int h = (bhd >> 3) % H_;
    const int b = bhd / (8 * H_);
    const int q0 = blockIdx.y * 32;

    const float* Kbase = &g_K[(size_t)(b * H_ + h) * L_ * DH_ + d * 8];

    for (int i = t; i < L_ * 2; i += 256) {
        int k = i >> 1, half = (i & 1) * 4;
        *reinterpret_cast<float4*>(&sk[k * 12 + half]) =
            *reinterpret_cast<const float4*>(&Kbase[(size_t)k * DH_ + half]);
    }
    sq[t] = g_Q[(size_t)((b * H_ + h) * L_ + q0 + (t >> 3)) * DH_ + d * 8 + (t & 7)];
    for (int i = t; i < L_; i += 256) smask[i] = mask[b * L_ + i];
    __syncthreads();

    const int warp = t >> 5, lane = t & 31;
    const int r0 = warp * 4;

    float qr[4][8];
    #pragma unroll
    for (int r = 0; r < 4; r++)
        #pragma unroll
        for (int s = 0; s < 8; s++) qr[r][s] = sq[(r0 + r) * 8 + s];

    float m[4], S[4], E1[4], E2[4];
    #pragma unroll
    for (int r = 0; r < 4; r++) { m[r] = -1e30f; S[r] = 0.f; E1[r] = 0.f; E2[r] = 0.f; }

    for (int kb = 0; kb < L_; kb += 32) {
        int k = kb + lane;
        float4 ka  = *reinterpret_cast<const float4*>(&sk[k * 12]);
        float4 kb4 = *reinterpret_cast<const float4*>(&sk[k * 12 + 4]);
        float mk = smask[k];
        #pragma unroll
        for (int r = 0; r < 4; r++) {
            float s = qr[r][0] * ka.x;
            s = fmaf(qr[r][1], ka.y, s);
            s = fmaf(qr[r][2], ka.z, s);
            s = fmaf(qr[r][3], ka.w, s);
            s = fmaf(qr[r][4], kb4.x, s);
            s = fmaf(qr[r][5], kb4.y, s);
            s = fmaf(qr[r][6], kb4.z, s);
            s = fmaf(qr[r][7], kb4.w, s);
            s = fmaf(s, INV_SQRT_DS, mk);
            if (s > m[r]) {
                float rr = __expf(m[r] - s);        // 0 on first element
                float dd = s - m[r];
                E1[r] = rr * (E1[r] - dd * S[r]);
                S[r]  = fmaf(rr, S[r], 1.0f);
                E2[r] = fmaf(rr * rr, E2[r], 1.0f);
                m[r]  = s;
            } else {
                float e = __expf(s - m[r]);
                S[r]  += e;
                E1[r] += e * (s - m[r]);
                E2[r] += e * e;
            }
        }
    }

    // butterfly merge across lanes
    #pragma unroll
    for (int r = 0; r < 4; r++) {
        #pragma unroll
        for (int off = 16; off > 0; off >>= 1) {
            float mo  = __shfl_xor_sync(0xffffffff, m[r],  off);
            float So  = __shfl_xor_sync(0xffffffff, S[r],  off);
            float E1o = __shfl_xor_sync(0xffffffff, E1[r], off);
            float E2o = __shfl_xor_sync(0xffffffff, E2[r], off);
            float mn = fmaxf(m[r], mo);
            float ra = __expf(m[r] - mn);
            float rb = __expf(mo   - mn);
            float Sa = S[r];
            E1[r] = ra * (E1[r] - (mn - m[r]) * Sa) + rb * (E1o - (mn - mo) * So);
            E2[r] = ra * ra * E2[r] + rb * rb * E2o;
            S[r]  = ra * Sa + rb * So;
            m[r]  = mn;
        }
    }

    if (lane == 0) {
        float psum[4] = {0.f, 0.f, 0.f, 0.f};
        #pragma unroll
        for (int r = 0; r < 4; r++) {
            int row  = q0 + r0 + r;
            int ridx = ((b * H_ + h) * D_ + d) * L_ + row;
            g_mS[2 * ridx]     = m[r];
            g_mS[2 * ridx + 1] = S[r];
            float inv  = 1.0f / S[r];
            float maxp = inv;
            float hhi  = E2[r] * inv * inv;
            float var  = (hhi - (1.0f / (float)L_)) * (1.0f / (float)(L_ - 1));
            float ent  = __logf(S[r]) - E1[r] * inv;
            psum[0] += var; psum[1] += maxp; psum[2] += hhi; psum[3] += ent;
        }
        #pragma unroll
        for (int i = 0; i < 4; i++) sred[warp][i] = psum[i];
    }
    __syncthreads();
    if (t == 0) {
        double tot[4] = {0, 0, 0, 0};
        #pragma unroll
        for (int w = 0; w < 8; w++)
            #pragma unroll
            for (int i = 0; i < 4; i++) tot[i] += (double)sred[w][i];
        #pragma unroll
        for (int i = 0; i < 4; i++)
            atomicAdd(&g_acc[(b * D_ + d) * 4 + i], tot[i]);
    }
}

// ============================================================================
// K3: depth gate weights.
// ============================================================================
__global__ void weights_kernel()
{
    int lane = threadIdx.x;
    int b  = (lane >> 3) & 1;
    int dd = lane & 7;
    const float scale = 1.0f / (float)(H_ * L_);
    float st[4];
    #pragma unroll
    for (int i = 0; i < 4; i++)
        st[i] = (float)(g_acc[(b * D_ + dd) * 4 + i]) * scale;

    float n[4];
    #pragma unroll
    for (int i = 0; i < 4; i++) {
        float vmin = st[i], vmax = st[i];
        #pragma unroll
        for (int off = 1; off < 8; off <<= 1) {
            vmin = fminf(vmin, __shfl_xor_sync(0xffffffff, vmin, off));
            vmax = fmaxf(vmax, __shfl_xor_sync(0xffffffff, vmax, off));
        }
        n[i] = (st[i] - vmin) / fmaxf(vmax - vmin, 1e-12f);
    }
    float score = 0.5f * n[0] + 0.3f * n[1] + 0.2f * n[2] - 0.4f * n[3];
    float smax = score;
    #pragma unroll
    for (int off = 1; off < 8; off <<= 1)
        smax = fmaxf(smax, __shfl_xor_sync(0xffffffff, smax, off));
    float e = __expf(ALPHA_ * (score - smax));
    float ssum = e;
    #pragma unroll
    for (int off = 1; off < 8; off <<= 1)
        ssum += __shfl_xor_sync(0xffffffff, ssum, off);
    if (lane < 16) g_w[b * D_ + dd] = e / ssum;
}

// ============================================================================
// K4: recompute scores for all 8 depths, combine into attn4 with w_d/S_d.
// Stage attn tile in shared (sA, aliased onto sK which is dead post-score),
// write attn4 coalesced, then ctx = attn4 @ V with FULL k coverage per thread.
// grid.x = B*H (24), grid.y = L/32 (24).
// ============================================================================
#define QT 32
#define KT 128
#define KPAD 68
#define APAD 132

__global__ __launch_bounds__(256, 2) void attn_kernel(
    const float* __restrict__ mask,
    float* __restrict__ out_ctx,
    float* __restrict__ out_attn)
{
    extern __shared__ float smem_[];
    float* sQ   = smem_;                 // QT*64
    float* sM   = sQ   + QT * DH_;       // QT*8
    float* sMul = sM   + QT * D_;        // QT*8
    float* sK   = sMul + QT * D_;        // KT*KPAD (8704) — aliased by sA
    float* sV   = sK   + KT * KPAD;      // KT*KPAD
    float* smk  = sV   + KT * KPAD;      // KT
    float* sA   = sK;                    // QT*APAD (4224) <= KT*KPAD

    const int t  = threadIdx.x;
    const int bh = blockIdx.x;
    const int b  = bh / H_;
    const int q0 = blockIdx.y * QT;

    const float* Qbase = &g_Q[(size_t)(bh * L_ + q0) * DH_];
    const float* Kbase = &g_K[(size_t)bh * L_ * DH_];
    const float* Vbase = &g_V[(size_t)bh * L_ * DH_];

    for (int i = t; i < QT * DH_ / 4; i += 256)
        *reinterpret_cast<float4*>(&sQ[i * 4]) =
            *reinterpret_cast<const float4*>(&Qbase[i * 4]);
    {
        int q = t >> 3, dd = t & 7;
        int ridx = (bh * D_ + dd) * L_ + q0 + q;
        float mm = g_mS[2 * ridx];
        float SS = g_mS[2 * ridx + 1];
        sM[q * 8 + dd]   = mm;
        sMul[q * 8 + dd] = g_w[b * D_ + dd] / SS;
    }

    const int q   = t >> 3;
    const int kl0 = t & 7;
    const int dh0 = (t & 7) * 8;
    const int qg  = q0 + q;
    float ctx[8];
    #pragma unroll
    for (int i = 0; i < 8; i++) ctx[i] = 0.f;

    for (int kt = 0; kt < L_; kt += KT) {
        __syncthreads();
        for (int i = t; i < KT * DH_ / 4; i += 256) {
            int k = i >> 4, c = (i & 15) * 4;
            *reinterpret_cast<float4*>(&sK[k * KPAD + c]) =
                *reinterpret_cast<const float4*>(&Kbase[(size_t)(kt + k) * DH_ + c]);
            *reinterpret_cast<float4*>(&sV[k * KPAD + c]) =
                *reinterpret_cast<const float4*>(&Vbase[(size_t)(kt + k) * DH_ + c]);
        }
        if (t < KT) smk[t] = mask[b * L_ + kt + t];
        __syncthreads();

        float acc[16];
        #pragma unroll
        for (int j = 0; j < 16; j++) acc[j] = 0.f;

        #pragma unroll
        for (int dd = 0; dd < D_; dd++) {
            float q8[8];
            #pragma unroll
            for (int s = 0; s < 8; s++) q8[s] = sQ[q * DH_ + dd * 8 + s];
            float mm = sM[q * 8 + dd];
            float mu = sMul[q * 8 + dd];
            #pragma unroll
            for (int j = 0; j < 16; j++) {
                int k = kl0 + j * 8;
                const float* kp = &sK[k * KPAD + dd * 8];
                float4 ka  = *reinterpret_cast<const float4*>(kp);
                float4 kb4 = *reinterpret_cast<const float4*>(kp + 4);
                float s = q8[0] * ka.x;
                s = fmaf(q8[1], ka.y, s);
                s = fmaf(q8[2], ka.z, s);
                s = fmaf(q8[3], ka.w, s);
                s = fmaf(q8[4], kb4.x, s);
                s = fmaf(q8[5], kb4.y, s);
                s = fmaf(q8[6], kb4.z, s);
                s = fmaf(q8[7], kb4.w, s);
                s = fmaf(s, INV_SQRT_DS, smk[k] - mm);
                acc[j] = fmaf(mu, __expf(s), acc[j]);
            }
        }

        // sK is dead now; stage attn tile into sA (same memory)
        __syncthreads();
        #pragma unroll
        for (int j = 0; j < 16; j++)
            sA[q * APAD + kl0 + j * 8] = acc[j];
        __syncthreads();

        // coalesced attn4 write from sA
        for (int i = t; i < QT * KT / 4; i += 256) {
            int qq = i >> 5;           // (i*4)/128
            int kk = (i & 31) * 4;
            *reinterpret_cast<float4*>(
                &out_attn[(size_t)(bh * L_ + q0 + qq) * L_ + kt + kk]) =
                *reinterpret_cast<const float4*>(&sA[qq * APAD + kk]);
        }

        // ctx accumulation: FULL k coverage for this thread's (q, dh0..dh0+7)
        #pragma unroll 4
        for (int kk = 0; kk < KT; kk += 4) {
            float4 a = *reinterpret_cast<const float4*>(&sA[q * APAD + kk]);
            #pragma unroll
            for (int u = 0; u < 4; u++) {
                float av = (u == 0) ? a.x : (u == 1) ? a.y : (u == 2) ? a.z : a.w;
                const float* vp = &sV[(kk + u) * KPAD + dh0];
                float4 va = *reinterpret_cast<const float4*>(vp);
                float4 vb = *reinterpret_cast<const float4*>(vp + 4);
                ctx[0] = fmaf(av, va.x, ctx[0]);
                ctx[1] = fmaf(av, va.y, ctx[1]);
                ctx[2] = fmaf(av, va.z, ctx[2]);
                ctx[3] = fmaf(av, va.w, ctx[3]);
                ctx[4] = fmaf(av, vb.x, ctx[4]);
                ctx[5] = fmaf(av, vb.y, ctx[5]);
                ctx[6] = fmaf(av, vb.z, ctx[6]);
                ctx[7] = fmaf(av, vb.w, ctx[7]);
            }
        }
    }

    float* op = &out_ctx[(size_t)(b * L_ + qg) * E_ + (bh % H_) * DH_ + dh0];
    *reinterpret_cast<float4*>(op)     = make_float4(ctx[0], ctx[1], ctx[2], ctx[3]);
    *reinterpret_cast<float4*>(op + 4) = make_float4(ctx[4], ctx[5], ctx[6], ctx[7]);
}

// ============================================================================
extern "C" void kernel_launch(void* const* d_in, const int* in_sizes, int n_in,
                              void* d_out, int out_size)
{
    const float* hs   = (const float*)d_in[0];
    const float* mask = (const float*)d_in[1];
    const float* Wq   = (const float*)d_in[2];
    const float* bq   = (const float*)d_in[3];
    const float* Wk   = (const float*)d_in[4];
    const float* bk   = (const float*)d_in[5];
    const float* Wv   = (const float*)d_in[6];
    const float* bv   = (const float*)d_in[7];

    float* out_ctx  = (float*)d_out;
    float* out_attn = out_ctx + (size_t)B_ * L_ * E_;

    proj_kernel<<<dim3(E_ / PBN, (B_ * L_) / PBM, 3), 256>>>(hs, Wq, bq, Wk, bk, Wv, bv);
    stats_kernel<<<dim3(B_ * H_ * D_, L_ / 32), 256>>>(mask);
    weights_kernel<<<1, 32>>>();

    const int smem_bytes = (QT * DH_ + 2 * QT * D_ + 2 * KT * KPAD + KT) * (int)sizeof(float);
    cudaFuncSetAttribute(attn_kernel, cudaFuncAttributeMaxDynamicSharedMemorySize, smem_bytes);
    attn_kernel<<<dim3(B_ * H_, L_ / QT), 256, smem_bytes>>>(mask, out_ctx, out_attn);
}

// round 3
// speedup vs baseline: 1.4160x; 1.4160x over previous
#include <cuda_runtime.h>
#include <math.h>

#define B_  2
#define L_  768
#define E_  768
#define H_  12
#define DH_ 64
#define D_  8
#define DS_ 8
#define INV_SQRT_DS 0.35355339059327373f
#define ALPHA_ 2.5f

// ---------------- scratch (static device globals; no allocation) -------------
__device__ float  g_Q[B_*H_*L_*DH_];
__device__ float  g_K[B_*H_*L_*DH_];
__device__ float  g_V[B_*H_*L_*DH_];
__device__ float  g_mS[B_*H_*D_*L_*2];   // per (b,h,d,q): rowmax m, denom S
__device__ double g_acc[B_*D_*4];        // sums over (h,q): var, max, hhi, ent
__device__ float  g_w[B_*D_];            // depth gate weights

// ============================================================================
// K1: fused Q/K/V projections (unchanged this round).
// ============================================================================
#define PBM 128
#define PBN 64
#define PBK 8

__global__ __launch_bounds__(256) void proj_kernel(
    const float* __restrict__ X,
    const float* __restrict__ Wq, const float* __restrict__ bq,
    const float* __restrict__ Wk, const float* __restrict__ bk,
    const float* __restrict__ Wv, const float* __restrict__ bv)
{
    __shared__ float As[PBK][PBM];
    __shared__ float Bs[PBK][PBN];
    const int t = threadIdx.x;

    if (blockIdx.x == 0 && blockIdx.y == 0 && blockIdx.z == 0 && t < B_*D_*4)
        g_acc[t] = 0.0;

    const float* W; const float* bias; float* out;
    if (blockIdx.z == 0)      { W = Wq; bias = bq; out = g_Q; }
    else if (blockIdx.z == 1) { W = Wk; bias = bk; out = g_K; }
    else                      { W = Wv; bias = bv; out = g_V; }

    const int row0 = blockIdx.y * PBM;
    const int col0 = blockIdx.x * PBN;
    const int ty = t >> 4, tx = t & 15;

    float acc[8][4];
    #pragma unroll
    for (int i = 0; i < 8; i++)
        #pragma unroll
        for (int j = 0; j < 4; j++) acc[i][j] = 0.f;

    const int am = t >> 1, akq = (t & 1) * 4;

    for (int kk = 0; kk < E_; kk += PBK) {
        float4 av = *reinterpret_cast<const float4*>(&X[(size_t)(row0 + am) * E_ + kk + akq]);
        As[akq + 0][am] = av.x; As[akq + 1][am] = av.y;
        As[akq + 2][am] = av.z; As[akq + 3][am] = av.w;
        if (t < 128) {
            int bkk = t >> 4, bn4 = (t & 15) * 4;
            *reinterpret_cast<float4*>(&Bs[bkk][bn4]) =
                *reinterpret_cast<const float4*>(&W[(size_t)(kk + bkk) * E_ + col0 + bn4]);
        }
        __syncthreads();
        #pragma unroll
        for (int k = 0; k < PBK; k++) {
            float a[8], b4[4];
            #pragma unroll
            for (int i = 0; i < 8; i++) a[i] = As[k][ty * 8 + i];
            #pragma unroll
            for (int j = 0; j < 4; j++) b4[j] = Bs[k][tx * 4 + j];
            #pragma unroll
            for (int i = 0; i < 8; i++)
                #pragma unroll
                for (int j = 0; j < 4; j++)
                    acc[i][j] = fmaf(a[i], b4[j], acc[i][j]);
        }
        __syncthreads();
    }

    const int h = col0 / DH_;
    #pragma unroll
    for (int i = 0; i < 8; i++) {
        int row = row0 + ty * 8 + i;
        int b = row / L_, l = row % L_;
        float4 o;
        o.x = acc[i][0] + bias[col0 + tx * 4 + 0];
        o.y = acc[i][1] + bias[col0 + tx * 4 + 1];
        o.z = acc[i][2] + bias[col0 + tx * 4 + 2];
        o.w = acc[i][3] + bias[col0 + tx * 4 + 3];
        *reinterpret_cast<float4*>(&out[(size_t)((b * H_ + h) * L_ + l) * DH_ + tx * 4]) = o;
    }
}

// ============================================================================
// K2: per-row online softmax statistics (unchanged this round).
// ============================================================================
__global__ __launch_bounds__(256) void stats_kernel(const float* __restrict__ mask)
{
    __shared__ float sk[L_ * 12];
    __shared__ float sq[32 * 8];
    __shared__ float smask[L_];
    __shared__ float sred[8][4];

    const int t = threadIdx.x;
    const int bhd = blockIdx.x;
    const int d = bhd & 7;
    const int h = (bhd >> 3) % H_;
    const int b = bhd / (8 * H_);
    const int q0 = blockIdx.y * 32;

    const float* Kbase = &g_K[(size_t)(b * H_ + h) * L_ * DH_ + d * 8];

    for (int i = t; i < L_ * 2; i += 256) {
        int k = i >> 1, half = (i & 1) * 4;
        *reinterpret_cast<float4*>(&sk[k * 12 + half]) =
            *reinterpret_cast<const float4*>(&Kbase[(size_t)k * DH_ + half]);
    }
    sq[t] = g_Q[(size_t)((b * H_ + h) * L_ + q0 + (t >> 3)) * DH_ + d * 8 + (t & 7)];
    for (int i = t; i < L_; i += 256) smask[i] = mask[b * L_ + i];
    __syncthreads();

    const int warp = t >> 5, lane = t & 31;
    const int r0 = warp * 4;

    float qr[4][8];
    #pragma unroll
    for (int r = 0; r < 4; r++)
        #pragma unroll
        for (int s = 0; s < 8; s++) qr[r][s] = sq[(r0 + r) * 8 + s];

    float m[4], S[4], E1[4], E2[4];
    #pragma unroll
    for (int r = 0; r < 4; r++) { m[r] = -1e30f; S[r] = 0.f; E1[r] = 0.f; E2[r] = 0.f; }

    for (int kb = 0; kb < L_; kb += 32) {
        int k = kb + lane;
        float4 ka  = *reinterpret_cast<const float4*>(&sk[k * 12]);
        float4 kb4 = *reinterpret_cast<const float4*>(&sk[k * 12 + 4]);
        float mk = smask[k];
        #pragma unroll
        for (int r = 0; r < 4; r++) {
            float s = qr[r][0] * ka.x;
            s = fmaf(qr[r][1], ka.y, s);
            s = fmaf(qr[r][2], ka.z, s);
            s = fmaf(qr[r][3], ka.w, s);
            s = fmaf(qr[r][4], kb4.x, s);
            s = fmaf(qr[r][5], kb4.y, s);
            s = fmaf(qr[r][6], kb4.z, s);
            s = fmaf(qr[r][7], kb4.w, s);
            s = fmaf(s, INV_SQRT_DS, mk);
            if (s > m[r]) {
                float rr = __expf(m[r] - s);
                float dd = s - m[r];
                E1[r] = rr * (E1[r] - dd * S[r]);
                S[r]  = fmaf(rr, S[r], 1.0f);
                E2[r] = fmaf(rr * rr, E2[r], 1.0f);
                m[r]  = s;
            } else {
                float e = __expf(s - m[r]);
                S[r]  += e;
                E1[r] += e * (s - m[r]);
                E2[r] += e * e;
            }
        }
    }

    #pragma unroll
    for (int r = 0; r < 4; r++) {
        #pragma unroll
        for (int off = 16; off > 0; off >>= 1) {
            float mo  = __shfl_xor_sync(0xffffffff, m[r],  off);
            float So  = __shfl_xor_sync(0xffffffff, S[r],  off);
            float E1o = __shfl_xor_sync(0xffffffff, E1[r], off);
            float E2o = __shfl_xor_sync(0xffffffff, E2[r], off);
            float mn = fmaxf(m[r], mo);
            float ra = __expf(m[r] - mn);
            float rb = __expf(mo   - mn);
            float Sa = S[r];
            E1[r] = ra * (E1[r] - (mn - m[r]) * Sa) + rb * (E1o - (mn - mo) * So);
            E2[r] = ra * ra * E2[r] + rb * rb * E2o;
            S[r]  = ra * Sa + rb * So;
            m[r]  = mn;
        }
    }

    if (lane == 0) {
        float psum[4] = {0.f, 0.f, 0.f, 0.f};
        #pragma unroll
        for (int r = 0; r < 4; r++) {
            int row  = q0 + r0 + r;
            int ridx = ((b * H_ + h) * D_ + d) * L_ + row;
            g_mS[2 * ridx]     = m[r];
            g_mS[2 * ridx + 1] = S[r];
            float inv  = 1.0f / S[r];
            float maxp = inv;
            float hhi  = E2[r] * inv * inv;
            float var  = (hhi - (1.0f / (float)L_)) * (1.0f / (float)(L_ - 1));
            float ent  = __logf(S[r]) - E1[r] * inv;
            psum[0] += var; psum[1] += maxp; psum[2] += hhi; psum[3] += ent;
        }
        #pragma unroll
        for (int i = 0; i < 4; i++) sred[warp][i] = psum[i];
    }
    __syncthreads();
    if (t == 0) {
        double tot[4] = {0, 0, 0, 0};
        #pragma unroll
        for (int w = 0; w < 8; w++)
            #pragma unroll
            for (int i = 0; i < 4; i++) tot[i] += (double)sred[w][i];
        #pragma unroll
        for (int i = 0; i < 4; i++)
            atomicAdd(&g_acc[(b * D_ + d) * 4 + i], tot[i]);
    }
}

// ============================================================================
// K3: depth gate weights (unchanged).
// ============================================================================
__global__ void weights_kernel()
{
    int lane = threadIdx.x;
    int b  = (lane >> 3) & 1;
    int dd = lane & 7;
    const float scale = 1.0f / (float)(H_ * L_);
    float st[4];
    #pragma unroll
    for (int i = 0; i < 4; i++)
        st[i] = (float)(g_acc[(b * D_ + dd) * 4 + i]) * scale;

    float n[4];
    #pragma unroll
    for (int i = 0; i < 4; i++) {
        float vmin = st[i], vmax = st[i];
        #pragma unroll
        for (int off = 1; off < 8; off <<= 1) {
            vmin = fminf(vmin, __shfl_xor_sync(0xffffffff, vmin, off));
            vmax = fmaxf(vmax, __shfl_xor_sync(0xffffffff, vmax, off));
        }
        n[i] = (st[i] - vmin) / fmaxf(vmax - vmin, 1e-12f);
    }
    float score = 0.5f * n[0] + 0.3f * n[1] + 0.2f * n[2] - 0.4f * n[3];
    float smax = score;
    #pragma unroll
    for (int off = 1; off < 8; off <<= 1)
        smax = fmaxf(smax, __shfl_xor_sync(0xffffffff, smax, off));
    float e = __expf(ALPHA_ * (score - smax));
    float ssum = e;
    #pragma unroll
    for (int off = 1; off < 8; off <<= 1)
        ssum += __shfl_xor_sync(0xffffffff, ssum, off);
    if (lane < 16) g_w[b * D_ + dd] = e / ssum;
}

// ============================================================================
// K4 (REWRITTEN): register-blocked 4q x 4k score tile per thread.
//   warp (t>>5) -> q rows 4w..4w+3; lane -> k = lane + 32*kj (kj=0..3).
//   attn4 written straight from registers (coalesced).
//   acc staged q-major sA[q*132+k] (conflict-free STS, broadcast reads).
//   ctx: thread (q4=t>>5, kspl=lane>>3, dhc=lane&7) owns 4q x 8dh over
//   k in {32j + 8*kspl + r}; shfl_xor(8,16) reduces over kspl at the end.
// ============================================================================
#define QT 32
#define KT 128
#define KPAD 68
#define APAD 132

__global__ __launch_bounds__(256, 2) void attn_kernel(
    const float* __restrict__ mask,
    float* __restrict__ out_ctx,
    float* __restrict__ out_attn)
{
    extern __shared__ float smem_[];
    float* sQ   = smem_;                 // QT*64
    float* sM   = sQ   + QT * DH_;       // QT*8
    float* sMul = sM   + QT * D_;        // QT*8
    float* sK   = sMul + QT * D_;        // KT*KPAD (8704) — aliased by sA
    float* sV   = sK   + KT * KPAD;      // KT*KPAD
    float* smk  = sV   + KT * KPAD;      // KT
    float* sA   = sK;                    // QT*APAD (4224) <= KT*KPAD

    const int t    = threadIdx.x;
    const int bh   = blockIdx.x;
    const int b    = bh / H_;
    const int q0   = blockIdx.y * QT;
    const int w    = t >> 5;             // warp -> q group
    const int lane = t & 31;
    const int kspl = lane >> 3;          // ctx k-split
    const int dhc  = lane & 7;           // ctx dh group

    const float* Qbase = &g_Q[(size_t)(bh * L_ + q0) * DH_];
    const float* Kbase = &g_K[(size_t)bh * L_ * DH_];
    const float* Vbase = &g_V[(size_t)bh * L_ * DH_];

    for (int i = t; i < QT * DH_ / 4; i += 256)
        *reinterpret_cast<float4*>(&sQ[i * 4]) =
            *reinterpret_cast<const float4*>(&Qbase[i * 4]);
    {
        int q = t >> 3, dd = t & 7;
        int ridx = (bh * D_ + dd) * L_ + q0 + q;
        float mm = g_mS[2 * ridx];
        float SS = g_mS[2 * ridx + 1];
        sM[q * 8 + dd]   = mm;
        sMul[q * 8 + dd] = g_w[b * D_ + dd] / SS;
    }

    float ctx[4][8];
    #pragma unroll
    for (int qi = 0; qi < 4; qi++)
        #pragma unroll
        for (int j = 0; j < 8; j++) ctx[qi][j] = 0.f;

    for (int kt = 0; kt < L_; kt += KT) {
        __syncthreads();
        for (int i = t; i < KT * DH_ / 4; i += 256) {
            int k = i >> 4, c = (i & 15) * 4;
            *reinterpret_cast<float4*>(&sK[k * KPAD + c]) =
                *reinterpret_cast<const float4*>(&Kbase[(size_t)(kt + k) * DH_ + c]);
            *reinterpret_cast<float4*>(&sV[k * KPAD + c]) =
                *reinterpret_cast<const float4*>(&Vbase[(size_t)(kt + k) * DH_ + c]);
        }
        if (t < KT) smk[t] = mask[b * L_ + kt + t];
        __syncthreads();

        // ---------------- score phase: acc[4 q][4 k] ----------------
        float acc[4][4];
        #pragma unroll
        for (int qi = 0; qi < 4; qi++)
            #pragma unroll
            for (int kj = 0; kj < 4; kj++) acc[qi][kj] = 0.f;

        float mk[4];
        #pragma unroll
        for (int kj = 0; kj < 4; kj++) mk[kj] = smk[lane + 32 * kj];

        #pragma unroll
        for (int dd = 0; dd < D_; dd++) {
            float q8[4][8], mm[4], mu[4];
            #pragma unroll
            for (int qi = 0; qi < 4; qi++) {
                const float* qp = &sQ[(4 * w + qi) * DH_ + dd * 8];
                float4 qa = *reinterpret_cast<const float4*>(qp);
                float4 qb = *reinterpret_cast<const float4*>(qp + 4);
                q8[qi][0] = qa.x; q8[qi][1] = qa.y; q8[qi][2] = qa.z; q8[qi][3] = qa.w;
                q8[qi][4] = qb.x; q8[qi][5] = qb.y; q8[qi][6] = qb.z; q8[qi][7] = qb.w;
                mm[qi] = sM[(4 * w + qi) * 8 + dd];
                mu[qi] = sMul[(4 * w + qi) * 8 + dd];
            }
            #pragma unroll
            for (int kj = 0; kj < 4; kj++) {
                const float* kp = &sK[(lane + 32 * kj) * KPAD + dd * 8];
                float4 ka  = *reinterpret_cast<const float4*>(kp);
                float4 kb4 = *reinterpret_cast<const float4*>(kp + 4);
                #pragma unroll
                for (int qi = 0; qi < 4; qi++) {
                    float s = q8[qi][0] * ka.x;
                    s = fmaf(q8[qi][1], ka.y, s);
                    s = fmaf(q8[qi][2], ka.z, s);
                    s = fmaf(q8[qi][3], ka.w, s);
                    s = fmaf(q8[qi][4], kb4.x, s);
                    s = fmaf(q8[qi][5], kb4.y, s);
                    s = fmaf(q8[qi][6], kb4.z, s);
                    s = fmaf(q8[qi][7], kb4.w, s);
                    s = fmaf(s, INV_SQRT_DS, mk[kj] - mm[qi]);
                    acc[qi][kj] = fmaf(mu[qi], __expf(s), acc[qi][kj]);
                }
            }
        }

        // attn4 write straight from registers: lane<->k fully coalesced
        #pragma unroll
        for (int qi = 0; qi < 4; qi++) {
            float* row = &out_attn[(size_t)(bh * L_ + q0 + 4 * w + qi) * L_ + kt];
            #pragma unroll
            for (int kj = 0; kj < 4; kj++)
                row[lane + 32 * kj] = acc[qi][kj];
        }

        // stage acc into sA (q-major; STS banks = (4q+lane)%32, conflict-free)
        __syncthreads();   // sK reads done before overwriting via alias
        #pragma unroll
        for (int qi = 0; qi < 4; qi++)
            #pragma unroll
            for (int kj = 0; kj < 4; kj++)
                sA[(4 * w + qi) * APAD + lane + 32 * kj] = acc[qi][kj];
        __syncthreads();

        // ---------------- ctx phase: thread (w, kspl, dhc) ----------------
        #pragma unroll
        for (int j = 0; j < 4; j++) {
            #pragma unroll
            for (int r = 0; r < 8; r++) {
                int k = 32 * j + 8 * kspl + r;
                float a0 = sA[(4 * w + 0) * APAD + k];   // broadcast reads
                float a1 = sA[(4 * w + 1) * APAD + k];
                float a2 = sA[(4 * w + 2) * APAD + k];
                float a3 = sA[(4 * w + 3) * APAD + k];
                const float* vp = &sV[k * KPAD + dhc * 4];
                float4 v0 = *reinterpret_cast<const float4*>(vp);        // dh: dhc*4..+3
                float4 v1 = *reinterpret_cast<const float4*>(vp + 32);   // dh: 32+dhc*4..+3
                float av[4] = {a0, a1, a2, a3};
                #pragma unroll
                for (int qi = 0; qi < 4; qi++) {
                    ctx[qi][0] = fmaf(av[qi], v0.x, ctx[qi][0]);
                    ctx[qi][1] = fmaf(av[qi], v0.y, ctx[qi][1]);
                    ctx[qi][2] = fmaf(av[qi], v0.z, ctx[qi][2]);
                    ctx[qi][3] = fmaf(av[qi], v0.w, ctx[qi][3]);
                    ctx[qi][4] = fmaf(av[qi], v1.x, ctx[qi][4]);
                    ctx[qi][5] = fmaf(av[qi], v1.y, ctx[qi][5]);
                    ctx[qi][6] = fmaf(av[qi], v1.z, ctx[qi][6]);
                    ctx[qi][7] = fmaf(av[qi], v1.w, ctx[qi][7]);
                }
            }
        }
    }

    // reduce ctx over kspl (lane bits 3,4) via butterfly
    #pragma unroll
    for (int qi = 0; qi < 4; qi++)
        #pragma unroll
        for (int j = 0; j < 8; j++) {
            ctx[qi][j] += __shfl_xor_sync(0xffffffff, ctx[qi][j], 8);
            ctx[qi][j] += __shfl_xor_sync(0xffffffff, ctx[qi][j], 16);
        }

    // lane (kspl,dhc) writes q row 4w+kspl, cols dhc*4 and dhc*4+32
    {
        int qg = q0 + 4 * w + kspl;
        float* op = &out_ctx[(size_t)(b * L_ + qg) * E_ + (bh % H_) * DH_ + dhc * 4];
        *reinterpret_cast<float4*>(op) =
            make_float4(ctx[kspl][0], ctx[kspl][1], ctx[kspl][2], ctx[kspl][3]);
        *reinterpret_cast<float4*>(op + 32) =
            make_float4(ctx[kspl][4], ctx[kspl][5], ctx[kspl][6], ctx[kspl][7]);
    }
}

// ============================================================================
extern "C" void kernel_launch(void* const* d_in, const int* in_sizes, int n_in,
                              void* d_out, int out_size)
{
    const float* hs   = (const float*)d_in[0];
    const float* mask = (const float*)d_in[1];
    const float* Wq   = (const float*)d_in[2];
    const float* bq   = (const float*)d_in[3];
    const float* Wk   = (const float*)d_in[4];
    const float* bk   = (const float*)d_in[5];
    const float* Wv   = (const float*)d_in[6];
    const float* bv   = (const float*)d_in[7];

    float* out_ctx  = (float*)d_out;
    float* out_attn = out_ctx + (size_t)B_ * L_ * E_;

    proj_kernel<<<dim3(E_ / PBN, (B_ * L_) / PBM, 3), 256>>>(hs, Wq, bq, Wk, bk, Wv, bv);
    stats_kernel<<<dim3(B_ * H_ * D_, L_ / 32), 256>>>(mask);
    weights_kernel<<<1, 32>>>();

    const int smem_bytes = (QT * DH_ + 2 * QT * D_ + 2 * KT * KPAD + KT) * (int)sizeof(float);
    cudaFuncSetAttribute(attn_kernel, cudaFuncAttributeMaxDynamicSharedMemorySize, smem_bytes);
    attn_kernel<<<dim3(B_ * H_, L_ / QT), 256, smem_bytes>>>(mask, out_ctx, out_attn);
}

// round 6
// speedup vs baseline: 1.8739x; 1.3234x over previous
#include <cuda_runtime.h>
#include <math.h>

#define B_  2
#define L_  768
#define E_  768
#define H_  12
#define DH_ 64
#define D_  8
#define DS_ 8
#define INV_SQRT_DS 0.35355339059327373f
#define ALPHA_ 2.5f

// ---------------- scratch (static device globals; no allocation) -------------
__device__ float  g_Q[B_*H_*L_*DH_];
__device__ float  g_K[B_*H_*L_*DH_];
__device__ float  g_V[B_*H_*L_*DH_];
__device__ float  g_S[B_*H_*D_*L_];      // per (b,h,d,q): softmax denom (m=0)
__device__ double g_acc[B_*D_*4];        // sums over (h,q): var, max, hhi, ent
__device__ float  g_w[B_*D_];            // depth gate weights

// ============================================================================
// K1: fused Q/K/V projections.  BK=16 double-buffered.
// ============================================================================
#define PBM 128
#define PBN 64
#define PBK 16

__global__ __launch_bounds__(256) void proj_kernel(
    const float* __restrict__ X,
    const float* __restrict__ Wq, const float* __restrict__ bq,
    const float* __restrict__ Wk, const float* __restrict__ bk,
    const float* __restrict__ Wv, const float* __restrict__ bv)
{
    __shared__ float As[2][PBK][PBM];
    __shared__ float Bs[2][PBK][PBN];
    const int t = threadIdx.x;

    if (blockIdx.x == 0 && blockIdx.y == 0 && blockIdx.z == 0 && t < B_*D_*4)
        g_acc[t] = 0.0;

    const float* W; const float* bias; float* out;
    if (blockIdx.z == 0)      { W = Wq; bias = bq; out = g_Q; }
    else if (blockIdx.z == 1) { W = Wk; bias = bk; out = g_K; }
    else                      { W = Wv; bias = bv; out = g_V; }

    const int row0 = blockIdx.y * PBM;
    const int col0 = blockIdx.x * PBN;
    const int ty = t >> 4, tx = t & 15;

    const int am  = t >> 1;
    const int ak0 = (t & 1) * 4;
    const int ak1 = ak0 + 8;
    const int bkk = t >> 4, bn4 = (t & 15) * 4;

    float acc[8][4];
    #pragma unroll
    for (int i = 0; i < 8; i++)
        #pragma unroll
        for (int j = 0; j < 4; j++) acc[i][j] = 0.f;

    float4 a0 = *reinterpret_cast<const float4*>(&X[(size_t)(row0 + am) * E_ + ak0]);
    float4 a1 = *reinterpret_cast<const float4*>(&X[(size_t)(row0 + am) * E_ + ak1]);
    float4 b0 = *reinterpret_cast<const float4*>(&W[(size_t)bkk * E_ + col0 + bn4]);

    int buf = 0;
    As[0][ak0 + 0][am] = a0.x; As[0][ak0 + 1][am] = a0.y;
    As[0][ak0 + 2][am] = a0.z; As[0][ak0 + 3][am] = a0.w;
    As[0][ak1 + 0][am] = a1.x; As[0][ak1 + 1][am] = a1.y;
    As[0][ak1 + 2][am] = a1.z; As[0][ak1 + 3][am] = a1.w;
    *reinterpret_cast<float4*>(&Bs[0][bkk][bn4]) = b0;
    __syncthreads();

    for (int kk = 0; kk < E_; kk += PBK) {
        const bool more = (kk + PBK) < E_;
        if (more) {
            a0 = *reinterpret_cast<const float4*>(&X[(size_t)(row0 + am) * E_ + kk + PBK + ak0]);
            a1 = *reinterpret_cast<const float4*>(&X[(size_t)(row0 + am) * E_ + kk + PBK + ak1]);
            b0 = *reinterpret_cast<const float4*>(&W[(size_t)(kk + PBK + bkk) * E_ + col0 + bn4]);
        }
        #pragma unroll
        for (int k = 0; k < PBK; k++) {
            float a[8], b4[4];
            #pragma unroll
            for (int i = 0; i < 8; i++) a[i] = As[buf][k][ty * 8 + i];
            #pragma unroll
            for (int j = 0; j < 4; j++) b4[j] = Bs[buf][k][tx * 4 + j];
            #pragma unroll
            for (int i = 0; i < 8; i++)
                #pragma unroll
                for (int j = 0; j < 4; j++)
                    acc[i][j] = fmaf(a[i], b4[j], acc[i][j]);
        }
        __syncthreads();
        if (more) {
            int nb = buf ^ 1;
            As[nb][ak0 + 0][am] = a0.x; As[nb][ak0 + 1][am] = a0.y;
            As[nb][ak0 + 2][am] = a0.z; As[nb][ak0 + 3][am] = a0.w;
            As[nb][ak1 + 0][am] = a1.x; As[nb][ak1 + 1][am] = a1.y;
            As[nb][ak1 + 2][am] = a1.z; As[nb][ak1 + 3][am] = a1.w;
            *reinterpret_cast<float4*>(&Bs[nb][bkk][bn4]) = b0;
            __syncthreads();
            buf = nb;
        }
    }

    const int h = col0 / DH_;
    #pragma unroll
    for (int i = 0; i < 8; i++) {
        int row = row0 + ty * 8 + i;
        int b = row / L_, l = row % L_;
        float4 o;
        o.x = acc[i][0] + bias[col0 + tx * 4 + 0];
        o.y = acc[i][1] + bias[col0 + tx * 4 + 1];
        o.z = acc[i][2] + bias[col0 + tx * 4 + 2];
        o.w = acc[i][3] + bias[col0 + tx * 4 + 3];
        *reinterpret_cast<float4*>(&out[(size_t)((b * H_ + h) * L_ + l) * DH_ + tx * 4]) = o;
    }
}

// ============================================================================
// K2: branchless stats, m=0 for exp (scores |s|<~3, safe), but TRUE row max
// tracked via fmaxf for the max_k statistic:  max p = exp(m)/S.
//   S = sum e, E1 = sum e*s, E2 = sum e^2, m = max s
//   hhi = E2/S^2, var = (hhi-1/L)/(L-1), ent = logS - E1/S, maxp = exp(m)/S
// ============================================================================
__global__ __launch_bounds__(256) void stats_kernel(const float* __restrict__ mask)
{
    __shared__ float sk[L_ * 12];
    __shared__ float sq[32 * 8];
    __shared__ float smask[L_];
    __shared__ float sred[8][4];

    const int t = threadIdx.x;
    const int bhd = blockIdx.x;
    const int d = bhd & 7;
    const int h = (bhd >> 3) % H_;
    const int b = bhd / (8 * H_);
    const int q0 = blockIdx.y * 32;

    const float* Kbase = &g_K[(size_t)(b * H_ + h) * L_ * DH_ + d * 8];

    for (int i = t; i < L_ * 2; i += 256) {
        int k = i >> 1, half = (i & 1) * 4;
        *reinterpret_cast<float4*>(&sk[k * 12 + half]) =
            *reinterpret_cast<const float4*>(&Kbase[(size_t)k * DH_ + half]);
    }
    sq[t] = g_Q[(size_t)((b * H_ + h) * L_ + q0 + (t >> 3)) * DH_ + d * 8 + (t & 7)];
    for (int i = t; i < L_; i += 256) smask[i] = mask[b * L_ + i];
    __syncthreads();

    const int warp = t >> 5, lane = t & 31;
    const int r0 = warp * 4;

    float qr[4][8];
    #pragma unroll
    for (int r = 0; r < 4; r++)
        #pragma unroll
        for (int s = 0; s < 8; s++) qr[r][s] = sq[(r0 + r) * 8 + s];

    float S[4]  = {0.f, 0.f, 0.f, 0.f};
    float E1[4] = {0.f, 0.f, 0.f, 0.f};
    float E2[4] = {0.f, 0.f, 0.f, 0.f};
    float M[4]  = {-1e30f, -1e30f, -1e30f, -1e30f};

    for (int kb = 0; kb < L_; kb += 32) {
        int k = kb + lane;
        float4 ka  = *reinterpret_cast<const float4*>(&sk[k * 12]);
        float4 kb4 = *reinterpret_cast<const float4*>(&sk[k * 12 + 4]);
        float mk = smask[k];
        #pragma unroll
        for (int r = 0; r < 4; r++) {
            float s = qr[r][0] * ka.x;
            s = fmaf(qr[r][1], ka.y, s);
            s = fmaf(qr[r][2], ka.z, s);
            s = fmaf(qr[r][3], ka.w, s);
            s = fmaf(qr[r][4], kb4.x, s);
            s = fmaf(qr[r][5], kb4.y, s);
            s = fmaf(qr[r][6], kb4.z, s);
            s = fmaf(qr[r][7], kb4.w, s);
            s = fmaf(s, INV_SQRT_DS, mk);
            float e = __expf(s);
            S[r]  += e;
            E1[r]  = fmaf(e, s, E1[r]);
            E2[r]  = fmaf(e, e, E2[r]);
            M[r]   = fmaxf(M[r], s);
        }
    }

    #pragma unroll
    for (int r = 0; r < 4; r++) {
        #pragma unroll
        for (int off = 16; off > 0; off >>= 1) {
            S[r]  += __shfl_xor_sync(0xffffffff, S[r],  off);
            E1[r] += __shfl_xor_sync(0xffffffff, E1[r], off);
            E2[r] += __shfl_xor_sync(0xffffffff, E2[r], off);
            M[r]   = fmaxf(M[r], __shfl_xor_sync(0xffffffff, M[r], off));
        }
    }

    if (lane == 0) {
        float psum[4] = {0.f, 0.f, 0.f, 0.f};
        #pragma unroll
        for (int r = 0; r < 4; r++) {
            int row  = q0 + r0 + r;
            int ridx = ((b * H_ + h) * D_ + d) * L_ + row;
            g_S[ridx] = S[r];
            float inv  = 1.0f / S[r];
            float maxp = __expf(M[r]) * inv;     // TRUE max_k p
            float hhi  = E2[r] * inv * inv;
            float var  = (hhi - (1.0f / (float)L_)) * (1.0f / (float)(L_ - 1));
            float ent  = __logf(S[r]) - E1[r] * inv;
            psum[0] += var; psum[1] += maxp; psum[2] += hhi; psum[3] += ent;
        }
        #pragma unroll
        for (int i = 0; i < 4; i++) sred[warp][i] = psum[i];
    }
    __syncthreads();
    if (t == 0) {
        double tot[4] = {0, 0, 0, 0};
        #pragma unroll
        for (int w = 0; w < 8; w++)
            #pragma unroll
            for (int i = 0; i < 4; i++) tot[i] += (double)sred[w][i];
        #pragma unroll
        for (int i = 0; i < 4; i++)
            atomicAdd(&g_acc[(b * D_ + d) * 4 + i], tot[i]);
    }
}

// ============================================================================
// K3: depth gate weights (unchanged).
// ============================================================================
__global__ void weights_kernel()
{
    int lane = threadIdx.x;
    int b  = (lane >> 3) & 1;
    int dd = lane & 7;
    const float scale = 1.0f / (float)(H_ * L_);
    float st[4];
    #pragma unroll
    for (int i = 0; i < 4; i++)
        st[i] = (float)(g_acc[(b * D_ + dd) * 4 + i]) * scale;

    float n[4];
    #pragma unroll
    for (int i = 0; i < 4; i++) {
        float vmin = st[i], vmax = st[i];
        #pragma unroll
        for (int off = 1; off < 8; off <<= 1) {
            vmin = fminf(vmin, __shfl_xor_sync(0xffffffff, vmin, off));
            vmax = fmaxf(vmax, __shfl_xor_sync(0xffffffff, vmax, off));
        }
        n[i] = (st[i] - vmin) / fmaxf(vmax - vmin, 1e-12f);
    }
    float score = 0.5f * n[0] + 0.3f * n[1] + 0.2f * n[2] - 0.4f * n[3];
    float smax = score;
    #pragma unroll
    for (int off = 1; off < 8; off <<= 1)
        smax = fmaxf(smax, __shfl_xor_sync(0xffffffff, smax, off));
    float e = __expf(ALPHA_ * (score - smax));
    float ssum = e;
    #pragma unroll
    for (int off = 1; off < 8; off <<= 1)
        ssum += __shfl_xor_sync(0xffffffff, ssum, off);
    if (lane < 16) g_w[b * D_ + dd] = e / ssum;
}

// ============================================================================
// K4: register-blocked 4q x 4k score tile; m=0 (no per-depth subtract).
// ============================================================================
#define QT 32
#define KT 128
#define KPAD 68
#define APAD 132

__global__ __launch_bounds__(256, 2) void attn_kernel(
    const float* __restrict__ mask,
    float* __restrict__ out_ctx,
    float* __restrict__ out_attn)
{
    extern __shared__ float smem_[];
    float* sQ   = smem_;                 // QT*64
    float* sMul = sQ   + QT * DH_;       // QT*8
    float* sK   = sMul + QT * D_;        // KT*KPAD — aliased by sA
    float* sV   = sK   + KT * KPAD;      // KT*KPAD
    float* smk  = sV   + KT * KPAD;      // KT
    float* sA   = sK;                    // QT*APAD <= KT*KPAD

    const int t    = threadIdx.x;
    const int bh   = blockIdx.x;
    const int b    = bh / H_;
    const int q0   = blockIdx.y * QT;
    const int w    = t >> 5;
    const int lane = t & 31;
    const int kspl = lane >> 3;
    const int dhc  = lane & 7;

    const float* Qbase = &g_Q[(size_t)(bh * L_ + q0) * DH_];
    const float* Kbase = &g_K[(size_t)bh * L_ * DH_];
    const float* Vbase = &g_V[(size_t)bh * L_ * DH_];

    for (int i = t; i < QT * DH_ / 4; i += 256)
        *reinterpret_cast<float4*>(&sQ[i * 4]) =
            *reinterpret_cast<const float4*>(&Qbase[i * 4]);
    {
        int q = t >> 3, dd = t & 7;
        int ridx = (bh * D_ + dd) * L_ + q0 + q;
        sMul[q * 8 + dd] = g_w[b * D_ + dd] / g_S[ridx];
    }

    float ctx[4][8];
    #pragma unroll
    for (int qi = 0; qi < 4; qi++)
        #pragma unroll
        for (int j = 0; j < 8; j++) ctx[qi][j] = 0.f;

    for (int kt = 0; kt < L_; kt += KT) {
        __syncthreads();
        for (int i = t; i < KT * DH_ / 4; i += 256) {
            int k = i >> 4, c = (i & 15) * 4;
            *reinterpret_cast<float4*>(&sK[k * KPAD + c]) =
                *reinterpret_cast<const float4*>(&Kbase[(size_t)(kt + k) * DH_ + c]);
            *reinterpret_cast<float4*>(&sV[k * KPAD + c]) =
                *reinterpret_cast<const float4*>(&Vbase[(size_t)(kt + k) * DH_ + c]);
        }
        if (t < KT) smk[t] = mask[b * L_ + kt + t];
        __syncthreads();

        float acc[4][4];
        #pragma unroll
        for (int qi = 0; qi < 4; qi++)
            #pragma unroll
            for (int kj = 0; kj < 4; kj++) acc[qi][kj] = 0.f;

        float mk[4];
        #pragma unroll
        for (int kj = 0; kj < 4; kj++) mk[kj] = smk[lane + 32 * kj];

        #pragma unroll
        for (int dd = 0; dd < D_; dd++) {
            float q8[4][8], mu[4];
            #pragma unroll
            for (int qi = 0; qi < 4; qi++) {
                const float* qp = &sQ[(4 * w + qi) * DH_ + dd * 8];
                float4 qa = *reinterpret_cast<const float4*>(qp);
                float4 qb = *reinterpret_cast<const float4*>(qp + 4);
                q8[qi][0] = qa.x; q8[qi][1] = qa.y; q8[qi][2] = qa.z; q8[qi][3] = qa.w;
                q8[qi][4] = qb.x; q8[qi][5] = qb.y; q8[qi][6] = qb.z; q8[qi][7] = qb.w;
                mu[qi] = sMul[(4 * w + qi) * 8 + dd];
            }
            #pragma unroll
            for (int kj = 0; kj < 4; kj++) {
                const float* kp = &sK[(lane + 32 * kj) * KPAD + dd * 8];
                float4 ka  = *reinterpret_cast<const float4*>(kp);
                float4 kb4 = *reinterpret_cast<const float4*>(kp + 4);
                #pragma unroll
                for (int qi = 0; qi < 4; qi++) {
                    float s = q8[qi][0] * ka.x;
                    s = fmaf(q8[qi][1], ka.y, s);
                    s = fmaf(q8[qi][2], ka.z, s);
                    s = fmaf(q8[qi][3], ka.w, s);
                    s = fmaf(q8[qi][4], kb4.x, s);
                    s = fmaf(q8[qi][5], kb4.y, s);
                    s = fmaf(q8[qi][6], kb4.z, s);
                    s = fmaf(q8[qi][7], kb4.w, s);
                    s = fmaf(s, INV_SQRT_DS, mk[kj]);
                    acc[qi][kj] = fmaf(mu[qi], __expf(s), acc[qi][kj]);
                }
            }
        }

        #pragma unroll
        for (int qi = 0; qi < 4; qi++) {
            float* row = &out_attn[(size_t)(bh * L_ + q0 + 4 * w + qi) * L_ + kt];
            #pragma unroll
            for (int kj = 0; kj < 4; kj++)
                row[lane + 32 * kj] = acc[qi][kj];
        }

        __syncthreads();
        #pragma unroll
        for (int qi = 0; qi < 4; qi++)
            #pragma unroll
            for (int kj = 0; kj < 4; kj++)
                sA[(4 * w + qi) * APAD + lane + 32 * kj] = acc[qi][kj];
        __syncthreads();

        #pragma unroll
        for (int j = 0; j < 4; j++) {
            #pragma unroll
            for (int r = 0; r < 8; r++) {
                int k = 32 * j + 8 * kspl + r;
                float a0 = sA[(4 * w + 0) * APAD + k];
                float a1 = sA[(4 * w + 1) * APAD + k];
                float a2 = sA[(4 * w + 2) * APAD + k];
                float a3 = sA[(4 * w + 3) * APAD + k];
                const float* vp = &sV[k * KPAD + dhc * 4];
                float4 v0 = *reinterpret_cast<const float4*>(vp);
                float4 v1 = *reinterpret_cast<const float4*>(vp + 32);
                float av[4] = {a0, a1, a2, a3};
                #pragma unroll
                for (int qi = 0; qi < 4; qi++) {
                    ctx[qi][0] = fmaf(av[qi], v0.x, ctx[qi][0]);
                    ctx[qi][1] = fmaf(av[qi], v0.y, ctx[qi][1]);
                    ctx[qi][2] = fmaf(av[qi], v0.z, ctx[qi][2]);
                    ctx[qi][3] = fmaf(av[qi], v0.w, ctx[qi][3]);
                    ctx[qi][4] = fmaf(av[qi], v1.x, ctx[qi][4]);
                    ctx[qi][5] = fmaf(av[qi], v1.y, ctx[qi][5]);
                    ctx[qi][6] = fmaf(av[qi], v1.z, ctx[qi][6]);
                    ctx[qi][7] = fmaf(av[qi], v1.w, ctx[qi][7]);
                }
            }
        }
    }

    #pragma unroll
    for (int qi = 0; qi < 4; qi++)
        #pragma unroll
        for (int j = 0; j < 8; j++) {
            ctx[qi][j] += __shfl_xor_sync(0xffffffff, ctx[qi][j], 8);
            ctx[qi][j] += __shfl_xor_sync(0xffffffff, ctx[qi][j], 16);
        }

    {
        int qg = q0 + 4 * w + kspl;
        float* op = &out_ctx[(size_t)(b * L_ + qg) * E_ + (bh % H_) * DH_ + dhc * 4];
        *reinterpret_cast<float4*>(op) =
            make_float4(ctx[kspl][0], ctx[kspl][1], ctx[kspl][2], ctx[kspl][3]);
        *reinterpret_cast<float4*>(op + 32) =
            make_float4(ctx[kspl][4], ctx[kspl][5], ctx[kspl][6], ctx[kspl][7]);
    }
}

// ============================================================================
extern "C" void kernel_launch(void* const* d_in, const int* in_sizes, int n_in,
                              void* d_out, int out_size)
{
    const float* hs   = (const float*)d_in[0];
    const float* mask = (const float*)d_in[1];
    const float* Wq   = (const float*)d_in[2];
    const float* bq   = (const float*)d_in[3];
    const float* Wk   = (const float*)d_in[4];
    const float* bk   = (const float*)d_in[5];
    const float* Wv   = (const float*)d_in[6];
    const float* bv   = (const float*)d_in[7];

    float* out_ctx  = (float*)d_out;
    float* out_attn = out_ctx + (size_t)B_ * L_ * E_;

    proj_kernel<<<dim3(E_ / PBN, (B_ * L_) / PBM, 3), 256>>>(hs, Wq, bq, Wk, bk, Wv, bv);
    stats_kernel<<<dim3(B_ * H_ * D_, L_ / 32), 256>>>(mask);
    weights_kernel<<<1, 32>>>();

    const int smem_bytes = (QT * DH_ + QT * D_ + 2 * KT * KPAD + KT) * (int)sizeof(float);
    cudaFuncSetAttribute(attn_kernel, cudaFuncAttributeMaxDynamicSharedMemorySize, smem_bytes);
    attn_kernel<<<dim3(B_ * H_, L_ / QT), 256, smem_bytes>>>(mask, out_ctx, out_attn);
}

// round 8
// speedup vs baseline: 2.0506x; 1.0943x over previous
#include <cuda_runtime.h>
#include <cuda_bf16.h>
#include <math.h>
#include <stdint.h>

#define B_  2
#define L_  768
#define E_  768
#define H_  12
#define DH_ 64
#define D_  8
#define DS_ 8
#define INV_SQRT_DS 0.35355339059327373f
#define ALPHA_ 2.5f

// ---------------- scratch (static device globals; no allocation) -------------
__device__ float  g_Q[B_*H_*L_*DH_];
__device__ float  g_K[B_*H_*L_*DH_];
__device__ float  g_V[B_*H_*L_*DH_];
__device__ float  g_S[B_*H_*D_*L_];      // per (b,h,d,q): softmax denom (m=0)
__device__ double g_acc[B_*D_*4];        // sums over (h,q): var, max, hhi, ent
__device__ float  g_w[B_*D_];            // depth gate weights

// bf16 hi/lo splits for tensor-core projections
__device__ __nv_bfloat16 g_Xh[(size_t)B_*L_*E_];
__device__ __nv_bfloat16 g_Xl[(size_t)B_*L_*E_];
__device__ __nv_bfloat16 g_Wh[(size_t)3*E_*E_];
__device__ __nv_bfloat16 g_Wl[(size_t)3*E_*E_];

__device__ __forceinline__ uint32_t smem_u32(const void* p) {
    uint32_t a;
    asm("{ .reg .u64 t; cvta.to.shared.u64 t, %1; cvt.u32.u64 %0, t; }"
        : "=r"(a) : "l"(p));
    return a;
}

// ============================================================================
// K0: split fp32 X and W into bf16 hi/lo; also zero g_acc.
// ============================================================================
#define NX4 ((B_*L_*E_) / 4)
#define NW4 ((E_*E_) / 4)

__global__ __launch_bounds__(256) void split_kernel(
    const float* __restrict__ X,
    const float* __restrict__ Wq, const float* __restrict__ Wk,
    const float* __restrict__ Wv)
{
    int idx = blockIdx.x * blockDim.x + threadIdx.x;
    if (blockIdx.x == 0 && threadIdx.x < B_*D_*4) g_acc[threadIdx.x] = 0.0;
    if (idx >= NX4 + 3 * NW4) return;

    const float* src;
    __nv_bfloat16 *dh, *dl;
    int off;
    if (idx < NX4) {
        src = X; dh = g_Xh; dl = g_Xl; off = idx * 4;
    } else {
        int j = idx - NX4;
        int w = j / NW4;
        off = (j - w * NW4) * 4;
        src = (w == 0) ? Wq : (w == 1) ? Wk : Wv;
        dh = g_Wh + (size_t)w * E_ * E_;
        dl = g_Wl + (size_t)w * E_ * E_;
    }
    float4 v = *reinterpret_cast<const float4*>(&src[off]);
    float f[4] = {v.x, v.y, v.z, v.w};
    ushort4 uh, ul;
    unsigned short* ph = &uh.x;
    unsigned short* pl = &ul.x;
    #pragma unroll
    for (int i = 0; i < 4; i++) {
        __nv_bfloat16 hi = __float2bfloat16(f[i]);
        __nv_bfloat16 lo = __float2bfloat16(f[i] - __bfloat162float(hi));
        ph[i] = __bfloat16_as_ushort(hi);
        pl[i] = __bfloat16_as_ushort(lo);
    }
    *reinterpret_cast<ushort4*>(&dh[off]) = uh;
    *reinterpret_cast<ushort4*>(&dl[off]) = ul;
}

// ============================================================================
// K1: mma.sync bf16 projection GEMM (portable PTX, no arch-'a' features).
// C[1536,768] = [Xh|Xh|Xl] @ [[Wh],[Wl],[Wh]]  (K = 3*768, phase-indexed).
// CTA tile 128x128, 8 warps (4m x 2n), warp tile 32x64 = 2x8 m16n8k16.
// BK=32 double-buffered smem, reg prefetch.
// ============================================================================
#define SA 40    // A smem row stride (bf16): 80B -> ldmatrix conflict-free
#define SB 136   // B smem row stride (bf16): 272B -> conflict-free
#define KITERS 72  // 2304 / 32

__global__ __launch_bounds__(256) void proj_mma_kernel(
    const float* __restrict__ bq, const float* __restrict__ bk,
    const float* __restrict__ bv)
{
    __shared__ __align__(16) __nv_bfloat16 As[2][128 * SA];
    __shared__ __align__(16) __nv_bfloat16 Bs[2][32 * SB];

    const int t = threadIdx.x, warp = t >> 5, lane = t & 31;
    const int wm = warp & 3, wn = warp >> 2;
    const int z = blockIdx.z;
    const int row0 = blockIdx.y * 128, col0 = blockIdx.x * 128;

    const __nv_bfloat16* Wh = g_Wh + (size_t)z * E_ * E_;
    const __nv_bfloat16* Wl = g_Wl + (size_t)z * E_ * E_;
    const float* bias = (z == 0) ? bq : (z == 1) ? bk : bv;
    float* out = (z == 0) ? g_Q : (z == 1) ? g_K : g_V;

    float acc[2][8][4];
    #pragma unroll
    for (int mt = 0; mt < 2; mt++)
        #pragma unroll
        for (int nt = 0; nt < 8; nt++)
            #pragma unroll
            for (int i = 0; i < 4; i++) acc[mt][nt][i] = 0.f;

    // load mappings
    const int ar0 = t >> 2, ak0 = (t & 3) * 8;     // A rows ar0, ar0+64
    const int bk0 = t >> 4, bn0 = (t & 15) * 8;    // B k-rows bk0, bk0+16

    uint4 ra0, ra1, rb0, rb1;
    {   // prefetch iteration 0 (phase 0: Xh @ Wh)
        ra0 = *reinterpret_cast<const uint4*>(&g_Xh[(size_t)(row0 + ar0) * E_ + ak0]);
        ra1 = *reinterpret_cast<const uint4*>(&g_Xh[(size_t)(row0 + ar0 + 64) * E_ + ak0]);
        rb0 = *reinterpret_cast<const uint4*>(&Wh[(size_t)bk0 * E_ + col0 + bn0]);
        rb1 = *reinterpret_cast<const uint4*>(&Wh[(size_t)(bk0 + 16) * E_ + col0 + bn0]);
    }
    *reinterpret_cast<uint4*>(&As[0][ar0 * SA + ak0]) = ra0;
    *reinterpret_cast<uint4*>(&As[0][(ar0 + 64) * SA + ak0]) = ra1;
    *reinterpret_cast<uint4*>(&Bs[0][bk0 * SB + bn0]) = rb0;
    *reinterpret_cast<uint4*>(&Bs[0][(bk0 + 16) * SB + bn0]) = rb1;
    __syncthreads();

    int buf = 0;
    for (int it = 0; it < KITERS; it++) {
        if (it + 1 < KITERS) {
            const int nit = it + 1;
            const int ph = nit / 24;
            const int k768 = (nit % 24) * 32;
            const __nv_bfloat16* Ap = (ph < 2) ? g_Xh : g_Xl;
            const __nv_bfloat16* Bp = (ph == 1) ? Wl : Wh;
            ra0 = *reinterpret_cast<const uint4*>(&Ap[(size_t)(row0 + ar0) * E_ + k768 + ak0]);
            ra1 = *reinterpret_cast<const uint4*>(&Ap[(size_t)(row0 + ar0 + 64) * E_ + k768 + ak0]);
            rb0 = *reinterpret_cast<const uint4*>(&Bp[(size_t)(k768 + bk0) * E_ + col0 + bn0]);
            rb1 = *reinterpret_cast<const uint4*>(&Bp[(size_t)(k768 + bk0 + 16) * E_ + col0 + bn0]);
        }

        // compute on buf: 2 k16 steps
        #pragma unroll
        for (int ks = 0; ks < 2; ks++) {
            uint32_t a[2][4];
            #pragma unroll
            for (int mt = 0; mt < 2; mt++) {
                uint32_t addr = smem_u32(
                    &As[buf][(wm * 32 + mt * 16 + (lane & 15)) * SA + ks * 16 + (lane >> 4) * 8]);
                asm volatile("ldmatrix.sync.aligned.m8n8.x4.shared.b16 {%0,%1,%2,%3}, [%4];"
                    : "=r"(a[mt][0]), "=r"(a[mt][1]), "=r"(a[mt][2]), "=r"(a[mt][3])
                    : "r"(addr));
            }
            #pragma unroll
            for (int nt = 0; nt < 8; nt++) {
                uint32_t b0, b1;
                uint32_t baddr = smem_u32(
                    &Bs[buf][(ks * 16 + (lane & 15)) * SB + wn * 64 + nt * 8]);
                asm volatile("ldmatrix.sync.aligned.m8n8.x2.trans.shared.b16 {%0,%1}, [%2];"
                    : "=r"(b0), "=r"(b1) : "r"(baddr));
                #pragma unroll
                for (int mt = 0; mt < 2; mt++) {
                    asm volatile(
                        "mma.sync.aligned.m16n8k16.row.col.f32.bf16.bf16.f32 "
                        "{%0,%1,%2,%3}, {%4,%5,%6,%7}, {%8,%9}, {%0,%1,%2,%3};"
                        : "+f"(acc[mt][nt][0]), "+f"(acc[mt][nt][1]),
                          "+f"(acc[mt][nt][2]), "+f"(acc[mt][nt][3])
                        : "r"(a[mt][0]), "r"(a[mt][1]), "r"(a[mt][2]), "r"(a[mt][3]),
                          "r"(b0), "r"(b1));
                }
            }
        }
        __syncthreads();
        if (it + 1 < KITERS) {
            int nb = buf ^ 1;
            *reinterpret_cast<uint4*>(&As[nb][ar0 * SA + ak0]) = ra0;
            *reinterpret_cast<uint4*>(&As[nb][(ar0 + 64) * SA + ak0]) = ra1;
            *reinterpret_cast<uint4*>(&Bs[nb][bk0 * SB + bn0]) = rb0;
            *reinterpret_cast<uint4*>(&Bs[nb][(bk0 + 16) * SB + bn0]) = rb1;
            __syncthreads();
            buf = nb;
        }
    }

    // epilogue: bias + store to [b,h,l,dh]
    #pragma unroll
    for (int mt = 0; mt < 2; mt++) {
        #pragma unroll
        for (int nt = 0; nt < 8; nt++) {
            int r = row0 + wm * 32 + mt * 16 + (lane >> 2);
            int c = col0 + wn * 64 + nt * 8 + (lane & 3) * 2;
            int h = c >> 6, dh = c & 63;
            float bz0 = bias[c], bz1 = bias[c + 1];
            #pragma unroll
            for (int half = 0; half < 2; half++) {
                int rr = r + half * 8;
                int b = rr / L_, l = rr % L_;
                float* op = &out[(size_t)((b * H_ + h) * L_ + l) * DH_ + dh];
                float2 v;
                v.x = acc[mt][nt][half * 2 + 0] + bz0;
                v.y = acc[mt][nt][half * 2 + 1] + bz1;
                *reinterpret_cast<float2*>(op) = v;
            }
        }
    }
}

// ============================================================================
// K2: branchless stats, m=0 for exp; true row max tracked for the max stat.
// ============================================================================
__global__ __launch_bounds__(256) void stats_kernel(const float* __restrict__ mask)
{
    __shared__ float sk[L_ * 12];
    __shared__ float sq[32 * 8];
    __shared__ float smask[L_];
    __shared__ float sred[8][4];

    const int t = threadIdx.x;
    const int bhd = blockIdx.x;
    const int d = bhd & 7;
    const int h = (bhd >> 3) % H_;
    const int b = bhd / (8 * H_);
    const int q0 = blockIdx.y * 32;

    const float* Kbase = &g_K[(size_t)(b * H_ + h) * L_ * DH_ + d * 8];

    for (int i = t; i < L_ * 2; i += 256) {
        int k = i >> 1, half = (i & 1) * 4;
        *reinterpret_cast<float4*>(&sk[k * 12 + half]) =
            *reinterpret_cast<const float4*>(&Kbase[(size_t)k * DH_ + half]);
    }
    sq[t] = g_Q[(size_t)((b * H_ + h) * L_ + q0 + (t >> 3)) * DH_ + d * 8 + (t & 7)];
    for (int i = t; i < L_; i += 256) smask[i] = mask[b * L_ + i];
    __syncthreads();

    const int warp = t >> 5, lane = t & 31;
    const int r0 = warp * 4;

    float qr[4][8];
    #pragma unroll
    for (int r = 0; r < 4; r++)
        #pragma unroll
        for (int s = 0; s < 8; s++) qr[r][s] = sq[(r0 + r) * 8 + s];

    float S[4]  = {0.f, 0.f, 0.f, 0.f};
    float E1[4] = {0.f, 0.f, 0.f, 0.f};
    float E2[4] = {0.f, 0.f, 0.f, 0.f};
    float M[4]  = {-1e30f, -1e30f, -1e30f, -1e30f};

    for (int kb = 0; kb < L_; kb += 32) {
        int k = kb + lane;
        float4 ka  = *reinterpret_cast<const float4*>(&sk[k * 12]);
        float4 kb4 = *reinterpret_cast<const float4*>(&sk[k * 12 + 4]);
        float mk = smask[k];
        #pragma unroll
        for (int r = 0; r < 4; r++) {
            float s = qr[r][0] * ka.x;
            s = fmaf(qr[r][1], ka.y, s);
            s = fmaf(qr[r][2], ka.z, s);
            s = fmaf(qr[r][3], ka.w, s);
            s = fmaf(qr[r][4], kb4.x, s);
            s = fmaf(qr[r][5], kb4.y, s);
            s = fmaf(qr[r][6], kb4.z, s);
            s = fmaf(qr[r][7], kb4.w, s);
            s = fmaf(s, INV_SQRT_DS, mk);
            float e = __expf(s);
            S[r]  += e;
            E1[r]  = fmaf(e, s, E1[r]);
            E2[r]  = fmaf(e, e, E2[r]);
            M[r]   = fmaxf(M[r], s);
        }
    }

    #pragma unroll
    for (int r = 0; r < 4; r++) {
        #pragma unroll
        for (int off = 16; off > 0; off >>= 1) {
            S[r]  += __shfl_xor_sync(0xffffffff, S[r],  off);
            E1[r] += __shfl_xor_sync(0xffffffff, E1[r], off);
            E2[r] += __shfl_xor_sync(0xffffffff, E2[r], off);
            M[r]   = fmaxf(M[r], __shfl_xor_sync(0xffffffff, M[r], off));
        }
    }

    if (lane == 0) {
        float psum[4] = {0.f, 0.f, 0.f, 0.f};
        #pragma unroll
        for (int r = 0; r < 4; r++) {
            int row  = q0 + r0 + r;
            int ridx = ((b * H_ + h) * D_ + d) * L_ + row;
            g_S[ridx] = S[r];
            float inv  = 1.0f / S[r];
            float maxp = __expf(M[r]) * inv;
            float hhi  = E2[r] * inv * inv;
            float var  = (hhi - (1.0f / (float)L_)) * (1.0f / (float)(L_ - 1));
            float ent  = __logf(S[r]) - E1[r] * inv;
            psum[0] += var; psum[1] += maxp; psum[2] += hhi; psum[3] += ent;
        }
        #pragma unroll
        for (int i = 0; i < 4; i++) sred[warp][i] = psum[i];
    }
    __syncthreads();
    if (t == 0) {
        double tot[4] = {0, 0, 0, 0};
        #pragma unroll
        for (int w = 0; w < 8; w++)
            #pragma unroll
            for (int i = 0; i < 4; i++) tot[i] += (double)sred[w][i];
        #pragma unroll
        for (int i = 0; i < 4; i++)
            atomicAdd(&g_acc[(b * D_ + d) * 4 + i], tot[i]);
    }
}

// ============================================================================
// K3: depth gate weights.
// ============================================================================
__global__ void weights_kernel()
{
    int lane = threadIdx.x;
    int b  = (lane >> 3) & 1;
    int dd = lane & 7;
    const float scale = 1.0f / (float)(H_ * L_);
    float st[4];
    #pragma unroll
    for (int i = 0; i < 4; i++)
        st[i] = (float)(g_acc[(b * D_ + dd) * 4 + i]) * scale;

    float n[4];
    #pragma unroll
    for (int i = 0; i < 4; i++) {
        float vmin = st[i], vmax = st[i];
        #pragma unroll
        for (int off = 1; off < 8; off <<= 1) {
            vmin = fminf(vmin, __shfl_xor_sync(0xffffffff, vmin, off));
            vmax = fmaxf(vmax, __shfl_xor_sync(0xffffffff, vmax, off));
        }
        n[i] = (st[i] - vmin) / fmaxf(vmax - vmin, 1e-12f);
    }
    float score = 0.5f * n[0] + 0.3f * n[1] + 0.2f * n[2] - 0.4f * n[3];
    float smax = score;
    #pragma unroll
    for (int off = 1; off < 8; off <<= 1)
        smax = fmaxf(smax, __shfl_xor_sync(0xffffffff, smax, off));
    float e = __expf(ALPHA_ * (score - smax));
    float ssum = e;
    #pragma unroll
    for (int off = 1; off < 8; off <<= 1)
        ssum += __shfl_xor_sync(0xffffffff, ssum, off);
    if (lane < 16) g_w[b * D_ + dd] = e / ssum;
}

// ============================================================================
// K4: register-blocked 4q x 4k score tile; m=0.
// ============================================================================
#define QT 32
#define KT 128
#define KPAD 68
#define APAD 132

__global__ __launch_bounds__(256, 2) void attn_kernel(
    const float* __restrict__ mask,
    float* __restrict__ out_ctx,
    float* __restrict__ out_attn)
{
    extern __shared__ float smem_[];
    float* sQ   = smem_;
    float* sMul = sQ   + QT * DH_;
    float* sK   = sMul + QT * D_;
    float* sV   = sK   + KT * KPAD;
    float* smk  = sV   + KT * KPAD;
    float* sA   = sK;

    const int t    = threadIdx.x;
    const int bh   = blockIdx.x;
    const int b    = bh / H_;
    const int q0   = blockIdx.y * QT;
    const int w    = t >> 5;
    const int lane = t & 31;
    const int kspl = lane >> 3;
    const int dhc  = lane & 7;

    const float* Qbase = &g_Q[(size_t)(bh * L_ + q0) * DH_];
    const float* Kbase = &g_K[(size_t)bh * L_ * DH_];
    const float* Vbase = &g_V[(size_t)bh * L_ * DH_];

    for (int i = t; i < QT * DH_ / 4; i += 256)
        *reinterpret_cast<float4*>(&sQ[i * 4]) =
            *reinterpret_cast<const float4*>(&Qbase[i * 4]);
    {
        int q = t >> 3, dd = t & 7;
        int ridx = (bh * D_ + dd) * L_ + q0 + q;
        sMul[q * 8 + dd] = g_w[b * D_ + dd] / g_S[ridx];
    }

    float ctx[4][8];
    #pragma unroll
    for (int qi = 0; qi < 4; qi++)
        #pragma unroll
        for (int j = 0; j < 8; j++) ctx[qi][j] = 0.f;

    for (int kt = 0; kt < L_; kt += KT) {
        __syncthreads();
        for (int i = t; i < KT * DH_ / 4; i += 256) {
            int k = i >> 4, c = (i & 15) * 4;
            *reinterpret_cast<float4*>(&sK[k * KPAD + c]) =
                *reinterpret_cast<const float4*>(&Kbase[(size_t)(kt + k) * DH_ + c]);
            *reinterpret_cast<float4*>(&sV[k * KPAD + c]) =
                *reinterpret_cast<const float4*>(&Vbase[(size_t)(kt + k) * DH_ + c]);
        }
        if (t < KT) smk[t] = mask[b * L_ + kt + t];
        __syncthreads();

        float acc[4][4];
        #pragma unroll
        for (int qi = 0; qi < 4; qi++)
            #pragma unroll
            for (int kj = 0; kj < 4; kj++) acc[qi][kj] = 0.f;

        float mk[4];
        #pragma unroll
        for (int kj = 0; kj < 4; kj++) mk[kj] = smk[lane + 32 * kj];

        #pragma unroll
        for (int dd = 0; dd < D_; dd++) {
            float q8[4][8], mu[4];
            #pragma unroll
            for (int qi = 0; qi < 4; qi++) {
                const float* qp = &sQ[(4 * w + qi) * DH_ + dd * 8];
                float4 qa = *reinterpret_cast<const float4*>(qp);
                float4 qb = *reinterpret_cast<const float4*>(qp + 4);
                q8[qi][0] = qa.x; q8[qi][1] = qa.y; q8[qi][2] = qa.z; q8[qi][3] = qa.w;
                q8[qi][4] = qb.x; q8[qi][5] = qb.y; q8[qi][6] = qb.z; q8[qi][7] = qb.w;
                mu[qi] = sMul[(4 * w + qi) * 8 + dd];
            }
            #pragma unroll
            for (int kj = 0; kj < 4; kj++) {
                const float* kp = &sK[(lane + 32 * kj) * KPAD + dd * 8];
                float4 ka  = *reinterpret_cast<const float4*>(kp);
                float4 kb4 = *reinterpret_cast<const float4*>(kp + 4);
                #pragma unroll
                for (int qi = 0; qi < 4; qi++) {
                    float s = q8[qi][0] * ka.x;
                    s = fmaf(q8[qi][1], ka.y, s);
                    s = fmaf(q8[qi][2], ka.z, s);
                    s = fmaf(q8[qi][3], ka.w, s);
                    s = fmaf(q8[qi][4], kb4.x, s);
                    s = fmaf(q8[qi][5], kb4.y, s);
                    s = fmaf(q8[qi][6], kb4.z, s);
                    s = fmaf(q8[qi][7], kb4.w, s);
                    s = fmaf(s, INV_SQRT_DS, mk[kj]);
                    acc[qi][kj] = fmaf(mu[qi], __expf(s), acc[qi][kj]);
                }
            }
        }

        #pragma unroll
        for (int qi = 0; qi < 4; qi++) {
            float* row = &out_attn[(size_t)(bh * L_ + q0 + 4 * w + qi) * L_ + kt];
            #pragma unroll
            for (int kj = 0; kj < 4; kj++)
                row[lane + 32 * kj] = acc[qi][kj];
        }

        __syncthreads();
        #pragma unroll
        for (int qi = 0; qi < 4; qi++)
            #pragma unroll
            for (int kj = 0; kj < 4; kj++)
                sA[(4 * w + qi) * APAD + lane + 32 * kj] = acc[qi][kj];
        __syncthreads();

        #pragma unroll
        for (int j = 0; j < 4; j++) {
            #pragma unroll
            for (int r = 0; r < 8; r++) {
                int k = 32 * j + 8 * kspl + r;
                float a0 = sA[(4 * w + 0) * APAD + k];
                float a1 = sA[(4 * w + 1) * APAD + k];
                float a2 = sA[(4 * w + 2) * APAD + k];
                float a3 = sA[(4 * w + 3) * APAD + k];
                const float* vp = &sV[k * KPAD + dhc * 4];
                float4 v0 = *reinterpret_cast<const float4*>(vp);
                float4 v1 = *reinterpret_cast<const float4*>(vp + 32);
                float av[4] = {a0, a1, a2, a3};
                #pragma unroll
                for (int qi = 0; qi < 4; qi++) {
                    ctx[qi][0] = fmaf(av[qi], v0.x, ctx[qi][0]);
                    ctx[qi][1] = fmaf(av[qi], v0.y, ctx[qi][1]);
                    ctx[qi][2] = fmaf(av[qi], v0.z, ctx[qi][2]);
                    ctx[qi][3] = fmaf(av[qi], v0.w, ctx[qi][3]);
                    ctx[qi][4] = fmaf(av[qi], v1.x, ctx[qi][4]);
                    ctx[qi][5] = fmaf(av[qi], v1.y, ctx[qi][5]);
                    ctx[qi][6] = fmaf(av[qi], v1.z, ctx[qi][6]);
                    ctx[qi][7] = fmaf(av[qi], v1.w, ctx[qi][7]);
                }
            }
        }
    }

    #pragma unroll
    for (int qi = 0; qi < 4; qi++)
        #pragma unroll
        for (int j = 0; j < 8; j++) {
            ctx[qi][j] += __shfl_xor_sync(0xffffffff, ctx[qi][j], 8);
            ctx[qi][j] += __shfl_xor_sync(0xffffffff, ctx[qi][j], 16);
        }

    {
        int qg = q0 + 4 * w + kspl;
        float* op = &out_ctx[(size_t)(b * L_ + qg) * E_ + (bh % H_) * DH_ + dhc * 4];
        *reinterpret_cast<float4*>(op) =
            make_float4(ctx[kspl][0], ctx[kspl][1], ctx[kspl][2], ctx[kspl][3]);
        *reinterpret_cast<float4*>(op + 32) =
            make_float4(ctx[kspl][4], ctx[kspl][5], ctx[kspl][6], ctx[kspl][7]);
    }
}

// ============================================================================
extern "C" void kernel_launch(void* const* d_in, const int* in_sizes, int n_in,
                              void* d_out, int out_size)
{
    const float* hs   = (const float*)d_in[0];
    const float* mask = (const float*)d_in[1];
    const float* Wq   = (const float*)d_in[2];
    const float* bq   = (const float*)d_in[3];
    const float* Wk   = (const float*)d_in[4];
    const float* bk   = (const float*)d_in[5];
    const float* Wv   = (const float*)d_in[6];
    const float* bv   = (const float*)d_in[7];

    float* out_ctx  = (float*)d_out;
    float* out_attn = out_ctx + (size_t)B_ * L_ * E_;

    const int nsplit = NX4 + 3 * NW4;
    split_kernel<<<(nsplit + 255) / 256, 256>>>(hs, Wq, Wk, Wv);

    proj_mma_kernel<<<dim3(E_ / 128, (B_ * L_) / 128, 3), 256>>>(bq, bk, bv);

    stats_kernel<<<dim3(B_ * H_ * D_, L_ / 32), 256>>>(mask);
    weights_kernel<<<1, 32>>>();

    const int smem_bytes = (QT * DH_ + QT * D_ + 2 * KT * KPAD + KT) * (int)sizeof(float);
    cudaFuncSetAttribute(attn_kernel, cudaFuncAttributeMaxDynamicSharedMemorySize, smem_bytes);
    attn_kernel<<<dim3(B_ * H_, L_ / QT), 256, smem_bytes>>>(mask, out_ctx, out_attn);
}